// round 3
// baseline (speedup 1.0000x reference)
#include <cuda_runtime.h>
#include <math.h>

// Problem constants
#define Bsz   2048
#define Hh    512
#define DIN   128
#define TT    96
#define DOUT  64
#define G3    1536   // 3*H

// ---------------------------------------------------------------------------
// Weight scratch (transposed K-major layouts), module-static device memory.
// ---------------------------------------------------------------------------
__device__ __align__(16) float g_Wih0_t[DIN * G3];   // [k=128][n=1536]
__device__ __align__(16) float g_Whh0_t[Hh  * G3];   // [k=512][n=1536]
__device__ __align__(16) float g_Wih1_t[Hh  * G3];   // [k=512][n=1536]
__device__ __align__(16) float g_Whh1_t[Hh  * G3];   // [k=512][n=1536]
__device__ __align__(16) float g_Wfc_t [Hh  * DIN];  // [k=512][o=128]
__device__ __align__(16) float g_Wpj_t [DIN * DOUT]; // [d=128][o=64]

// ---------------------------------------------------------------------------
// Reorg: transpose all weight matrices into K-major scratch. Runs every
// launch (deterministic, graph-capturable), ~2.6M elems => negligible cost.
// ---------------------------------------------------------------------------
__global__ void reorg_kernel(const float* __restrict__ Wih0,
                             const float* __restrict__ Whh0,
                             const float* __restrict__ Wih1,
                             const float* __restrict__ Whh1,
                             const float* __restrict__ Wfc,
                             const float* __restrict__ Wpj)
{
    int idx = blockIdx.x * blockDim.x + threadIdx.x;
    const int n0 = DIN * G3;     // 196608
    const int n1 = Hh * G3;      // 786432
    const int n4 = Hh * DIN;     // 65536
    const int n5 = DIN * DOUT;   // 8192

    if (idx < n0) {
        int k = idx / G3, n = idx - k * G3;
        g_Wih0_t[idx] = Wih0[n * DIN + k];
        return;
    }
    idx -= n0;
    if (idx < n1) {
        int k = idx / G3, n = idx - k * G3;
        g_Whh0_t[idx] = Whh0[n * Hh + k];
        return;
    }
    idx -= n1;
    if (idx < n1) {
        int k = idx / G3, n = idx - k * G3;
        g_Wih1_t[idx] = Wih1[n * Hh + k];
        return;
    }
    idx -= n1;
    if (idx < n1) {
        int k = idx / G3, n = idx - k * G3;
        g_Whh1_t[idx] = Whh1[n * Hh + k];
        return;
    }
    idx -= n1;
    if (idx < n4) {
        int k = idx / DIN, n = idx - k * DIN;   // n = output index o
        g_Wfc_t[idx] = Wfc[n * Hh + k];
        return;
    }
    idx -= n4;
    if (idx < n5) {
        int k = idx / DOUT, n = idx - k * DOUT; // n = output index o
        g_Wpj_t[idx] = Wpj[n * DIN + k];
    }
}

// ---------------------------------------------------------------------------
// Helpers
// ---------------------------------------------------------------------------
union F4 { float4 v; float f[4]; };

__device__ __forceinline__ float sigf(float x) {
    return __fdividef(1.0f, 1.0f + __expf(-x));
}
__device__ __forceinline__ float tanh_f(float x) {
    // tanh(x) = 2*sigmoid(2x) - 1 ; robust at |x| large (exp saturates cleanly)
    return __fdividef(2.0f, 1.0f + __expf(-2.0f * x)) - 1.0f;
}

// ---------------------------------------------------------------------------
// One GRU layer for 16 batch rows held in smem.
//   sx : [16][DX]  layer input
//   hc : [16][512] previous hidden (read-only here)
//   hn : [16][512] new hidden (written)
// Thread tile: 4 batches (ty in [0,4)) x 4 h-indices (tx in [0,64)) x 4 gate
// accumulators (r, z, i_n, h_n) = 64 fp32 accumulators.
// Two chunks of 256 h-indices cover H=512.
// ---------------------------------------------------------------------------
template <int DX>
__device__ __forceinline__ void gru_layer(const float* __restrict__ sx,
                                          const float* __restrict__ hc,
                                          float* __restrict__ hn,
                                          const float* __restrict__ Wih_t,
                                          const float* __restrict__ Whh_t,
                                          const float* __restrict__ b_ih,
                                          const float* __restrict__ b_hh,
                                          int tx, int ty)
{
    const int b0 = 4 * ty;
    const float4* __restrict__ Wih4 = (const float4*)Wih_t; // row stride 384 f4
    const float4* __restrict__ Whh4 = (const float4*)Whh_t;

#pragma unroll 1
    for (int c = 0; c < 2; ++c) {
        const int jq = c * 64 + tx;   // float4 column inside one gate block
        const int j0 = 4 * jq;        // scalar h-index base

        float aR[4][4], aZ[4][4], aIN[4][4], aHN[4][4];
#pragma unroll
        for (int i = 0; i < 4; ++i)
#pragma unroll
            for (int l = 0; l < 4; ++l) {
                aR[i][l] = 0.f; aZ[i][l] = 0.f; aIN[i][l] = 0.f; aHN[i][l] = 0.f;
            }

        // ---- pass 1: input GEMM (accumulate r, z, i_n) -----------------
#pragma unroll 2
        for (int k = 0; k < DX; k += 4) {
            F4 xv[4];
#pragma unroll
            for (int i = 0; i < 4; ++i)
                xv[i].v = *(const float4*)&sx[(b0 + i) * DX + k];
#pragma unroll
            for (int kk = 0; kk < 4; ++kk) {
                F4 wr, wz, wn;
                wr.v = __ldg(&Wih4[(k + kk) * 384 + jq]);
                wz.v = __ldg(&Wih4[(k + kk) * 384 + 128 + jq]);
                wn.v = __ldg(&Wih4[(k + kk) * 384 + 256 + jq]);
#pragma unroll
                for (int i = 0; i < 4; ++i) {
                    const float xs = xv[i].f[kk];
#pragma unroll
                    for (int l = 0; l < 4; ++l) {
                        aR[i][l]  = fmaf(xs, wr.f[l], aR[i][l]);
                        aZ[i][l]  = fmaf(xs, wz.f[l], aZ[i][l]);
                        aIN[i][l] = fmaf(xs, wn.f[l], aIN[i][l]);
                    }
                }
            }
        }

        // ---- pass 2: hidden GEMM (accumulate r, z, h_n) ----------------
#pragma unroll 2
        for (int k = 0; k < Hh; k += 4) {
            F4 hv[4];
#pragma unroll
            for (int i = 0; i < 4; ++i)
                hv[i].v = *(const float4*)&hc[(b0 + i) * Hh + k];
#pragma unroll
            for (int kk = 0; kk < 4; ++kk) {
                F4 wr, wz, wn;
                wr.v = __ldg(&Whh4[(k + kk) * 384 + jq]);
                wz.v = __ldg(&Whh4[(k + kk) * 384 + 128 + jq]);
                wn.v = __ldg(&Whh4[(k + kk) * 384 + 256 + jq]);
#pragma unroll
                for (int i = 0; i < 4; ++i) {
                    const float hs = hv[i].f[kk];
#pragma unroll
                    for (int l = 0; l < 4; ++l) {
                        aR[i][l]  = fmaf(hs, wr.f[l], aR[i][l]);
                        aZ[i][l]  = fmaf(hs, wz.f[l], aZ[i][l]);
                        aHN[i][l] = fmaf(hs, wn.f[l], aHN[i][l]);
                    }
                }
            }
        }

        // ---- gate math + write h_new -----------------------------------
        F4 bir, bhr, biz, bhz, bin, bhn;
        bir.v = __ldg((const float4*)(b_ih + j0));
        bhr.v = __ldg((const float4*)(b_hh + j0));
        biz.v = __ldg((const float4*)(b_ih + 512 + j0));
        bhz.v = __ldg((const float4*)(b_hh + 512 + j0));
        bin.v = __ldg((const float4*)(b_ih + 1024 + j0));
        bhn.v = __ldg((const float4*)(b_hh + 1024 + j0));

#pragma unroll
        for (int i = 0; i < 4; ++i) {
            F4 hold, hnew;
            hold.v = *(const float4*)&hc[(b0 + i) * Hh + j0];
#pragma unroll
            for (int l = 0; l < 4; ++l) {
                const float r = sigf(aR[i][l] + bir.f[l] + bhr.f[l]);
                const float z = sigf(aZ[i][l] + biz.f[l] + bhz.f[l]);
                const float nn = tanh_f(aIN[i][l] + bin.f[l]
                                        + r * (aHN[i][l] + bhn.f[l]));
                hnew.f[l] = nn + z * (hold.f[l] - nn);   // (1-z)n + z h
            }
            *(float4*)&hn[(b0 + i) * Hh + j0] = hnew.v;
        }
    }
}

// ---------------------------------------------------------------------------
// Main persistent kernel: 128 blocks x 16 batch rows, loops T=96 steps.
// smem: h0 double-buffer (2x16x512) + h1 double-buffer + x (16x128) = 136KB.
// ---------------------------------------------------------------------------
__global__ void __launch_bounds__(256, 1)
gru_main(const float* __restrict__ x,
         const float* __restrict__ b_ih0, const float* __restrict__ b_hh0,
         const float* __restrict__ b_ih1, const float* __restrict__ b_hh1,
         const float* __restrict__ b_fc,  const float* __restrict__ b_pj,
         float* __restrict__ y)
{
    extern __shared__ float sm[];
    float* h0A = sm;                 // 16*512
    float* h0B = sm + 8192;
    float* h1A = sm + 16384;
    float* h1B = sm + 24576;
    float* sx  = sm + 32768;         // 16*128

    const int tid = threadIdx.x;
    const int tx = tid & 63;
    const int ty = tid >> 6;
    const int gb0 = blockIdx.x * 16;

    // init: zero hidden states, load x[:,0,:]
    for (int i = tid; i < 8192; i += 256) { h0A[i] = 0.f; h1A[i] = 0.f; }
    for (int i = tid; i < 2048; i += 256) { sx[i] = x[gb0 * DIN + i]; }
    __syncthreads();

    float* h0c = h0A; float* h0n = h0B;
    float* h1c = h1A; float* h1n = h1B;

    for (int t = 0; t < TT; ++t) {
        // layer 0: sx (DX=128) -> h0n
        gru_layer<DIN>(sx, h0c, h0n, g_Wih0_t, g_Whh0_t, b_ih0, b_hh0, tx, ty);
        __syncthreads();

        // layer 1: h0n (DX=512) -> h1n
        gru_layer<Hh>(h0n, h1c, h1n, g_Wih1_t, g_Whh1_t, b_ih1, b_hh1, tx, ty);
        __syncthreads();

        // fc: out = h1n @ Wfc^T + b_fc  -> sx (next step input)
        {
            const int ox = tid & 31;      // 4*ox = output col base (128 cols)
            const int bz = tid >> 5;      // 2 batches per thread
            const int bb = 2 * bz;
            float acc[2][4];
#pragma unroll
            for (int i = 0; i < 2; ++i)
#pragma unroll
                for (int l = 0; l < 4; ++l) acc[i][l] = 0.f;

            const float4* __restrict__ W4 = (const float4*)g_Wfc_t; // [512][32]
#pragma unroll 2
            for (int k = 0; k < Hh; k += 4) {
                F4 hv0, hv1;
                hv0.v = *(const float4*)&h1n[bb * Hh + k];
                hv1.v = *(const float4*)&h1n[(bb + 1) * Hh + k];
#pragma unroll
                for (int kk = 0; kk < 4; ++kk) {
                    F4 w; w.v = __ldg(&W4[(k + kk) * 32 + ox]);
#pragma unroll
                    for (int l = 0; l < 4; ++l) {
                        acc[0][l] = fmaf(hv0.f[kk], w.f[l], acc[0][l]);
                        acc[1][l] = fmaf(hv1.f[kk], w.f[l], acc[1][l]);
                    }
                }
            }
            F4 bf; bf.v = __ldg(((const float4*)b_fc) + ox);
            F4 o0, o1;
#pragma unroll
            for (int l = 0; l < 4; ++l) {
                o0.f[l] = acc[0][l] + bf.f[l];
                o1.f[l] = acc[1][l] + bf.f[l];
            }
            // safe to overwrite sx: all threads passed the post-layer1 sync
            *(float4*)&sx[bb * DIN + 4 * ox]       = o0.v;
            *(float4*)&sx[(bb + 1) * DIN + 4 * ox] = o1.v;
        }
        __syncthreads();

        // projection: y[b][o][t] = sx[b] . Wpj_t[:,o] + b_pj[o]
        {
            const int bb = tid >> 4;      // 0..15
            const int ox = tid & 15;      // 4*ox = output col base (64 cols)
            F4 acc; acc.v = __ldg(((const float4*)b_pj) + ox);
            const float4* __restrict__ W4 = (const float4*)g_Wpj_t; // [128][16]
#pragma unroll 2
            for (int d = 0; d < DIN; d += 4) {
                F4 xv; xv.v = *(const float4*)&sx[bb * DIN + d];
#pragma unroll
                for (int kk = 0; kk < 4; ++kk) {
                    F4 w; w.v = __ldg(&W4[(d + kk) * 16 + ox]);
#pragma unroll
                    for (int l = 0; l < 4; ++l)
                        acc.f[l] = fmaf(xv.f[kk], w.f[l], acc.f[l]);
                }
            }
            const size_t base = ((size_t)(gb0 + bb) * DOUT + 4 * ox) * TT + t;
            y[base]          = acc.f[0];
            y[base + TT]     = acc.f[1];
            y[base + 2 * TT] = acc.f[2];
            y[base + 3 * TT] = acc.f[3];
        }

        // swap double buffers (no sync needed: proofs in analysis — the next
        // write to any buffer happens only after at least one __syncthreads)
        float* tp;
        tp = h0c; h0c = h0n; h0n = tp;
        tp = h1c; h1c = h1n; h1n = tp;
    }
}

// ---------------------------------------------------------------------------
// Entry point
// ---------------------------------------------------------------------------
extern "C" void kernel_launch(void* const* d_in, const int* in_sizes, int n_in,
                              void* d_out, int out_size)
{
    (void)in_sizes; (void)n_in; (void)out_size;

    const float* x     = (const float*)d_in[0];
    const float* Wih0  = (const float*)d_in[1];
    const float* Whh0  = (const float*)d_in[2];
    const float* bih0  = (const float*)d_in[3];
    const float* bhh0  = (const float*)d_in[4];
    const float* Wih1  = (const float*)d_in[5];
    const float* Whh1  = (const float*)d_in[6];
    const float* bih1  = (const float*)d_in[7];
    const float* bhh1  = (const float*)d_in[8];
    const float* Wfc   = (const float*)d_in[9];
    const float* bfc   = (const float*)d_in[10];
    const float* Wpj   = (const float*)d_in[11];
    const float* bpj   = (const float*)d_in[12];
    float* y = (float*)d_out;

    const int smem_bytes = (4 * 16 * Hh + 16 * DIN) * (int)sizeof(float); // 139264
    cudaFuncSetAttribute(gru_main,
                         cudaFuncAttributeMaxDynamicSharedMemorySize,
                         smem_bytes);

    // total reorg elements: 196608 + 3*786432 + 65536 + 8192 = 2629632
    reorg_kernel<<<2629632 / 256, 256>>>(Wih0, Whh0, Wih1, Whh1, Wfc, Wpj);

    gru_main<<<128, 256, smem_bytes>>>(x, bih0, bhh0, bih1, bhh1, bfc, bpj, y);
}

// round 4
// speedup vs baseline: 1.1295x; 1.1295x over previous
#include <cuda_runtime.h>
#include <math.h>

// Problem constants
#define Bsz   2048
#define Hh    512
#define DIN   128
#define TT    96
#define DOUT  64
#define G3    1536   // 3*H

typedef unsigned long long u64;

// ---------------------------------------------------------------------------
// Weight scratch (transposed K-major layouts), module-static device memory.
// ---------------------------------------------------------------------------
__device__ __align__(16) float g_Wih0_t[DIN * G3];   // [k=128][n=1536]
__device__ __align__(16) float g_Whh0_t[Hh  * G3];   // [k=512][n=1536]
__device__ __align__(16) float g_Wih1_t[Hh  * G3];   // [k=512][n=1536]
__device__ __align__(16) float g_Whh1_t[Hh  * G3];   // [k=512][n=1536]
__device__ __align__(16) float g_Wfc_t [Hh  * DIN];  // [k=512][o=128]
__device__ __align__(16) float g_Wpj_t [DIN * DOUT]; // [d=128][o=64]

// ---------------------------------------------------------------------------
// Reorg: transpose all weight matrices into K-major scratch.
// ---------------------------------------------------------------------------
__global__ void reorg_kernel(const float* __restrict__ Wih0,
                             const float* __restrict__ Whh0,
                             const float* __restrict__ Wih1,
                             const float* __restrict__ Whh1,
                             const float* __restrict__ Wfc,
                             const float* __restrict__ Wpj)
{
    int idx = blockIdx.x * blockDim.x + threadIdx.x;
    const int n0 = DIN * G3;     // 196608
    const int n1 = Hh * G3;      // 786432
    const int n4 = Hh * DIN;     // 65536
    const int n5 = DIN * DOUT;   // 8192

    if (idx < n0) {
        int k = idx / G3, n = idx - k * G3;
        g_Wih0_t[idx] = Wih0[n * DIN + k];
        return;
    }
    idx -= n0;
    if (idx < n1) {
        int k = idx / G3, n = idx - k * G3;
        g_Whh0_t[idx] = Whh0[n * Hh + k];
        return;
    }
    idx -= n1;
    if (idx < n1) {
        int k = idx / G3, n = idx - k * G3;
        g_Wih1_t[idx] = Wih1[n * Hh + k];
        return;
    }
    idx -= n1;
    if (idx < n1) {
        int k = idx / G3, n = idx - k * G3;
        g_Whh1_t[idx] = Whh1[n * Hh + k];
        return;
    }
    idx -= n1;
    if (idx < n4) {
        int k = idx / DIN, n = idx - k * DIN;   // n = output index o
        g_Wfc_t[idx] = Wfc[n * Hh + k];
        return;
    }
    idx -= n4;
    if (idx < n5) {
        int k = idx / DOUT, n = idx - k * DOUT; // n = output index o
        g_Wpj_t[idx] = Wpj[n * DIN + k];
    }
}

// ---------------------------------------------------------------------------
// Packed dual-fp32 helpers (Blackwell FFMA2 via PTX f32x2 — ptxas never
// auto-fuses this from C++; see SASS_QUICKREF "patterns absent").
// Numerics are bit-identical to two independent fmaf's.
// ---------------------------------------------------------------------------
union F4 { float4 v; float f[4]; u64 d[2]; };

__device__ __forceinline__ void ffma2(u64& acc, u64 a, u64 b) {
    asm("fma.rn.f32x2 %0, %1, %2, %0;" : "+l"(acc) : "l"(a), "l"(b));
}
__device__ __forceinline__ u64 pack2(float x) {
    u64 r;
    asm("mov.b64 %0, {%1, %1};" : "=l"(r) : "f"(x));
    return r;
}
__device__ __forceinline__ float2 unpack2(u64 p) {
    float lo, hi;
    asm("mov.b64 {%0, %1}, %2;" : "=f"(lo), "=f"(hi) : "l"(p));
    return make_float2(lo, hi);
}

__device__ __forceinline__ float sigf(float x) {
    return __fdividef(1.0f, 1.0f + __expf(-x));
}
__device__ __forceinline__ float tanh_f(float x) {
    return __fdividef(2.0f, 1.0f + __expf(-2.0f * x)) - 1.0f;
}

// ---------------------------------------------------------------------------
// One GRU layer for 16 batch rows held in smem (packed-FFMA2 version).
// Thread tile: 4 batches x 4 h-indices (2 f32x2 pairs) x 4 gate accumulators.
// ---------------------------------------------------------------------------
template <int DX>
__device__ __forceinline__ void gru_layer(const float* __restrict__ sx,
                                          const float* __restrict__ hc,
                                          float* __restrict__ hn,
                                          const float* __restrict__ Wih_t,
                                          const float* __restrict__ Whh_t,
                                          const float* __restrict__ b_ih,
                                          const float* __restrict__ b_hh,
                                          int tx, int ty)
{
    const int b0 = 4 * ty;
    const float4* __restrict__ Wih4 = (const float4*)Wih_t; // row stride 384 f4
    const float4* __restrict__ Whh4 = (const float4*)Whh_t;

#pragma unroll 1
    for (int c = 0; c < 2; ++c) {
        const int jq = c * 64 + tx;   // float4 column inside one gate block
        const int j0 = 4 * jq;        // scalar h-index base

        u64 aR[4][2], aZ[4][2], aIN[4][2], aHN[4][2];
#pragma unroll
        for (int i = 0; i < 4; ++i)
#pragma unroll
            for (int p = 0; p < 2; ++p) {
                aR[i][p] = 0ull; aZ[i][p] = 0ull;
                aIN[i][p] = 0ull; aHN[i][p] = 0ull;
            }

        // ---- pass 1: input GEMM (accumulate r, z, i_n) -----------------
#pragma unroll 2
        for (int k = 0; k < DX; k += 4) {
            F4 xv[4];
#pragma unroll
            for (int i = 0; i < 4; ++i)
                xv[i].v = *(const float4*)&sx[(b0 + i) * DX + k];
#pragma unroll
            for (int kk = 0; kk < 4; ++kk) {
                F4 wr, wz, wn;
                wr.v = __ldg(&Wih4[(k + kk) * 384 + jq]);
                wz.v = __ldg(&Wih4[(k + kk) * 384 + 128 + jq]);
                wn.v = __ldg(&Wih4[(k + kk) * 384 + 256 + jq]);
#pragma unroll
                for (int i = 0; i < 4; ++i) {
                    const u64 xs2 = pack2(xv[i].f[kk]);
#pragma unroll
                    for (int p = 0; p < 2; ++p) {
                        ffma2(aR[i][p],  xs2, wr.d[p]);
                        ffma2(aZ[i][p],  xs2, wz.d[p]);
                        ffma2(aIN[i][p], xs2, wn.d[p]);
                    }
                }
            }
        }

        // ---- pass 2: hidden GEMM (accumulate r, z, h_n) ----------------
#pragma unroll 2
        for (int k = 0; k < Hh; k += 4) {
            F4 hv[4];
#pragma unroll
            for (int i = 0; i < 4; ++i)
                hv[i].v = *(const float4*)&hc[(b0 + i) * Hh + k];
#pragma unroll
            for (int kk = 0; kk < 4; ++kk) {
                F4 wr, wz, wn;
                wr.v = __ldg(&Whh4[(k + kk) * 384 + jq]);
                wz.v = __ldg(&Whh4[(k + kk) * 384 + 128 + jq]);
                wn.v = __ldg(&Whh4[(k + kk) * 384 + 256 + jq]);
#pragma unroll
                for (int i = 0; i < 4; ++i) {
                    const u64 hs2 = pack2(hv[i].f[kk]);
#pragma unroll
                    for (int p = 0; p < 2; ++p) {
                        ffma2(aR[i][p],  hs2, wr.d[p]);
                        ffma2(aZ[i][p],  hs2, wz.d[p]);
                        ffma2(aHN[i][p], hs2, wn.d[p]);
                    }
                }
            }
        }

        // ---- gate math + write h_new -----------------------------------
        F4 bir, bhr, biz, bhz, bin, bhn;
        bir.v = __ldg((const float4*)(b_ih + j0));
        bhr.v = __ldg((const float4*)(b_hh + j0));
        biz.v = __ldg((const float4*)(b_ih + 512 + j0));
        bhz.v = __ldg((const float4*)(b_hh + 512 + j0));
        bin.v = __ldg((const float4*)(b_ih + 1024 + j0));
        bhn.v = __ldg((const float4*)(b_hh + 1024 + j0));

#pragma unroll
        for (int i = 0; i < 4; ++i) {
            F4 hold, hnew;
            hold.v = *(const float4*)&hc[(b0 + i) * Hh + j0];
#pragma unroll
            for (int p = 0; p < 2; ++p) {
                const float2 r2  = unpack2(aR[i][p]);
                const float2 z2  = unpack2(aZ[i][p]);
                const float2 in2 = unpack2(aIN[i][p]);
                const float2 hn2 = unpack2(aHN[i][p]);
                const float rv[2]  = { r2.x,  r2.y  };
                const float zv[2]  = { z2.x,  z2.y  };
                const float inv[2] = { in2.x, in2.y };
                const float hnv[2] = { hn2.x, hn2.y };
#pragma unroll
                for (int q = 0; q < 2; ++q) {
                    const int l = 2 * p + q;
                    const float r = sigf(rv[q] + bir.f[l] + bhr.f[l]);
                    const float z = sigf(zv[q] + biz.f[l] + bhz.f[l]);
                    const float nn = tanh_f(inv[q] + bin.f[l]
                                            + r * (hnv[q] + bhn.f[l]));
                    hnew.f[l] = nn + z * (hold.f[l] - nn);   // (1-z)n + z h
                }
            }
            *(float4*)&hn[(b0 + i) * Hh + j0] = hnew.v;
        }
    }
}

// ---------------------------------------------------------------------------
// Main persistent kernel: 128 blocks x 16 batch rows, loops T=96 steps.
// smem: h0 double-buffer (2x16x512) + h1 double-buffer + x (16x128) = 136KB.
// ---------------------------------------------------------------------------
__global__ void __launch_bounds__(256, 1)
gru_main(const float* __restrict__ x,
         const float* __restrict__ b_ih0, const float* __restrict__ b_hh0,
         const float* __restrict__ b_ih1, const float* __restrict__ b_hh1,
         const float* __restrict__ b_fc,  const float* __restrict__ b_pj,
         float* __restrict__ y)
{
    extern __shared__ float sm[];
    float* h0A = sm;                 // 16*512
    float* h0B = sm + 8192;
    float* h1A = sm + 16384;
    float* h1B = sm + 24576;
    float* sx  = sm + 32768;         // 16*128

    const int tid = threadIdx.x;
    const int tx = tid & 63;
    const int ty = tid >> 6;
    const int gb0 = blockIdx.x * 16;

    // init: zero hidden states, load x[:,0,:]
    for (int i = tid; i < 8192; i += 256) { h0A[i] = 0.f; h1A[i] = 0.f; }
    for (int i = tid; i < 2048; i += 256) { sx[i] = x[gb0 * DIN + i]; }
    __syncthreads();

    float* h0c = h0A; float* h0n = h0B;
    float* h1c = h1A; float* h1n = h1B;

    for (int t = 0; t < TT; ++t) {
        // layer 0: sx (DX=128) -> h0n
        gru_layer<DIN>(sx, h0c, h0n, g_Wih0_t, g_Whh0_t, b_ih0, b_hh0, tx, ty);
        __syncthreads();

        // layer 1: h0n (DX=512) -> h1n
        gru_layer<Hh>(h0n, h1c, h1n, g_Wih1_t, g_Whh1_t, b_ih1, b_hh1, tx, ty);
        __syncthreads();

        // fc: out = h1n @ Wfc^T + b_fc  -> sx (next step input)
        {
            const int ox = tid & 31;      // 4*ox = output col base (128 cols)
            const int bz = tid >> 5;      // 2 batches per thread
            const int bb = 2 * bz;
            u64 acc[2][2];
#pragma unroll
            for (int i = 0; i < 2; ++i)
#pragma unroll
                for (int p = 0; p < 2; ++p) acc[i][p] = 0ull;

            const float4* __restrict__ W4 = (const float4*)g_Wfc_t; // [512][32]
#pragma unroll 2
            for (int k = 0; k < Hh; k += 4) {
                F4 hv0, hv1;
                hv0.v = *(const float4*)&h1n[bb * Hh + k];
                hv1.v = *(const float4*)&h1n[(bb + 1) * Hh + k];
#pragma unroll
                for (int kk = 0; kk < 4; ++kk) {
                    F4 w; w.v = __ldg(&W4[(k + kk) * 32 + ox]);
                    const u64 h0p = pack2(hv0.f[kk]);
                    const u64 h1p = pack2(hv1.f[kk]);
                    ffma2(acc[0][0], h0p, w.d[0]);
                    ffma2(acc[0][1], h0p, w.d[1]);
                    ffma2(acc[1][0], h1p, w.d[0]);
                    ffma2(acc[1][1], h1p, w.d[1]);
                }
            }
            F4 bf; bf.v = __ldg(((const float4*)b_fc) + ox);
            F4 o0, o1;
#pragma unroll
            for (int p = 0; p < 2; ++p) {
                const float2 a0 = unpack2(acc[0][p]);
                const float2 a1 = unpack2(acc[1][p]);
                o0.f[2 * p]     = a0.x + bf.f[2 * p];
                o0.f[2 * p + 1] = a0.y + bf.f[2 * p + 1];
                o1.f[2 * p]     = a1.x + bf.f[2 * p];
                o1.f[2 * p + 1] = a1.y + bf.f[2 * p + 1];
            }
            // safe to overwrite sx: all threads passed the post-layer1 sync
            *(float4*)&sx[bb * DIN + 4 * ox]       = o0.v;
            *(float4*)&sx[(bb + 1) * DIN + 4 * ox] = o1.v;
        }
        __syncthreads();

        // projection: y[b][o][t] = sx[b] . Wpj_t[:,o] + b_pj[o]
        {
            const int bb = tid >> 4;      // 0..15
            const int ox = tid & 15;      // 4*ox = output col base (64 cols)
            F4 acc; acc.v = __ldg(((const float4*)b_pj) + ox);
            const float4* __restrict__ W4 = (const float4*)g_Wpj_t; // [128][16]
#pragma unroll 2
            for (int d = 0; d < DIN; d += 4) {
                F4 xv; xv.v = *(const float4*)&sx[bb * DIN + d];
#pragma unroll
                for (int kk = 0; kk < 4; ++kk) {
                    F4 w; w.v = __ldg(&W4[(d + kk) * 16 + ox]);
#pragma unroll
                    for (int l = 0; l < 4; ++l)
                        acc.f[l] = fmaf(xv.f[kk], w.f[l], acc.f[l]);
                }
            }
            const size_t base = ((size_t)(gb0 + bb) * DOUT + 4 * ox) * TT + t;
            y[base]          = acc.f[0];
            y[base + TT]     = acc.f[1];
            y[base + 2 * TT] = acc.f[2];
            y[base + 3 * TT] = acc.f[3];
        }

        // swap double buffers
        float* tp;
        tp = h0c; h0c = h0n; h0n = tp;
        tp = h1c; h1c = h1n; h1n = tp;
    }
}

// ---------------------------------------------------------------------------
// Entry point
// ---------------------------------------------------------------------------
extern "C" void kernel_launch(void* const* d_in, const int* in_sizes, int n_in,
                              void* d_out, int out_size)
{
    (void)in_sizes; (void)n_in; (void)out_size;

    const float* x     = (const float*)d_in[0];
    const float* Wih0  = (const float*)d_in[1];
    const float* Whh0  = (const float*)d_in[2];
    const float* bih0  = (const float*)d_in[3];
    const float* bhh0  = (const float*)d_in[4];
    const float* Wih1  = (const float*)d_in[5];
    const float* Whh1  = (const float*)d_in[6];
    const float* bih1  = (const float*)d_in[7];
    const float* bhh1  = (const float*)d_in[8];
    const float* Wfc   = (const float*)d_in[9];
    const float* bfc   = (const float*)d_in[10];
    const float* Wpj   = (const float*)d_in[11];
    const float* bpj   = (const float*)d_in[12];
    float* y = (float*)d_out;

    const int smem_bytes = (4 * 16 * Hh + 16 * DIN) * (int)sizeof(float); // 139264
    cudaFuncSetAttribute(gru_main,
                         cudaFuncAttributeMaxDynamicSharedMemorySize,
                         smem_bytes);

    // total reorg elements: 196608 + 3*786432 + 65536 + 8192 = 2629632
    reorg_kernel<<<2629632 / 256, 256>>>(Wih0, Whh0, Wih1, Whh1, Wfc, Wpj);

    gru_main<<<128, 256, smem_bytes>>>(x, bih0, bhh0, bih1, bhh1, bfc, bpj, y);
}

// round 5
// speedup vs baseline: 1.2225x; 1.0823x over previous
#include <cuda_runtime.h>
#include <math.h>

// Problem constants
#define Bsz   2048
#define Hh    512
#define DIN   128
#define TT    96
#define DOUT  64
#define G3    1536   // 3*H

typedef unsigned long long u64;

// ---------------------------------------------------------------------------
// Weight scratch (transposed K-major layouts), module-static device memory.
// ---------------------------------------------------------------------------
__device__ __align__(16) float g_Wih0_t[DIN * G3];   // [k=128][n=1536]
__device__ __align__(16) float g_Whh0_t[Hh  * G3];   // [k=512][n=1536]
__device__ __align__(16) float g_Wih1_t[Hh  * G3];   // [k=512][n=1536]
__device__ __align__(16) float g_Whh1_t[Hh  * G3];   // [k=512][n=1536]
__device__ __align__(16) float g_Wfc_t [Hh  * DIN];  // [k=512][o=128]
__device__ __align__(16) float g_Wpj_t [DIN * DOUT]; // [d=128][o=64]

// ---------------------------------------------------------------------------
// Reorg: transpose all weight matrices into K-major scratch.
// ---------------------------------------------------------------------------
__global__ void reorg_kernel(const float* __restrict__ Wih0,
                             const float* __restrict__ Whh0,
                             const float* __restrict__ Wih1,
                             const float* __restrict__ Whh1,
                             const float* __restrict__ Wfc,
                             const float* __restrict__ Wpj)
{
    int idx = blockIdx.x * blockDim.x + threadIdx.x;
    const int n0 = DIN * G3;     // 196608
    const int n1 = Hh * G3;      // 786432
    const int n4 = Hh * DIN;     // 65536
    const int n5 = DIN * DOUT;   // 8192

    if (idx < n0) {
        int k = idx / G3, n = idx - k * G3;
        g_Wih0_t[idx] = Wih0[n * DIN + k];
        return;
    }
    idx -= n0;
    if (idx < n1) {
        int k = idx / G3, n = idx - k * G3;
        g_Whh0_t[idx] = Whh0[n * Hh + k];
        return;
    }
    idx -= n1;
    if (idx < n1) {
        int k = idx / G3, n = idx - k * G3;
        g_Wih1_t[idx] = Wih1[n * Hh + k];
        return;
    }
    idx -= n1;
    if (idx < n1) {
        int k = idx / G3, n = idx - k * G3;
        g_Whh1_t[idx] = Whh1[n * Hh + k];
        return;
    }
    idx -= n1;
    if (idx < n4) {
        int k = idx / DIN, n = idx - k * DIN;   // n = output index o
        g_Wfc_t[idx] = Wfc[n * Hh + k];
        return;
    }
    idx -= n4;
    if (idx < n5) {
        int k = idx / DOUT, n = idx - k * DOUT; // n = output index o
        g_Wpj_t[idx] = Wpj[n * DIN + k];
    }
}

// ---------------------------------------------------------------------------
// Packed dual-fp32 helpers (FFMA2 via PTX f32x2).
// ---------------------------------------------------------------------------
union F4 { float4 v; float f[4]; u64 d[2]; };

__device__ __forceinline__ void ffma2(u64& acc, u64 a, u64 b) {
    asm("fma.rn.f32x2 %0, %1, %2, %0;" : "+l"(acc) : "l"(a), "l"(b));
}
__device__ __forceinline__ u64 pack2(float x) {
    u64 r;
    asm("mov.b64 %0, {%1, %1};" : "=l"(r) : "f"(x));
    return r;
}
__device__ __forceinline__ float2 unpack2(u64 p) {
    float lo, hi;
    asm("mov.b64 {%0, %1}, %2;" : "=f"(lo), "=f"(hi) : "l"(p));
    return make_float2(lo, hi);
}

__device__ __forceinline__ float sigf(float x) {
    return __fdividef(1.0f, 1.0f + __expf(-x));
}
__device__ __forceinline__ float tanh_f(float x) {
    return __fdividef(2.0f, 1.0f + __expf(-2.0f * x)) - 1.0f;
}

#define NB 8   // batches per thread

// ---------------------------------------------------------------------------
// One GRU layer for 16 batch rows held in smem.
// Thread map: tx in [0,128) = one float4 column per gate (covers full H=512),
//             ty in {0,1}   = 8-batch group.
// Weight redundancy across the CTA: 2x (was 4x) -> L1 traffic halved.
// Each 3-LDG weight group feeds 48 consecutive FFMA2 -> 2x latency tolerance.
// ---------------------------------------------------------------------------
template <int DX>
__device__ __forceinline__ void gru_layer(const float* __restrict__ sx,
                                          const float* __restrict__ hc,
                                          float* __restrict__ hn,
                                          const float* __restrict__ Wih_t,
                                          const float* __restrict__ Whh_t,
                                          const float* __restrict__ b_ih,
                                          const float* __restrict__ b_hh,
                                          int tx, int ty)
{
    const int b0 = NB * ty;
    const int jq = tx;            // float4 column inside one gate block
    const int j0 = 4 * tx;        // scalar h-index base
    const float4* __restrict__ Wih4 = (const float4*)Wih_t; // row stride 384 f4
    const float4* __restrict__ Whh4 = (const float4*)Whh_t;

    u64 aR[NB][2], aZ[NB][2], aIN[NB][2], aHN[NB][2];
#pragma unroll
    for (int i = 0; i < NB; ++i)
#pragma unroll
        for (int p = 0; p < 2; ++p) {
            aR[i][p] = 0ull; aZ[i][p] = 0ull;
            aIN[i][p] = 0ull; aHN[i][p] = 0ull;
        }

    // ---- pass 1: input GEMM (accumulate r, z, i_n) ---------------------
#pragma unroll 1
    for (int k = 0; k < DX; k += 4) {
        F4 xv[NB];
#pragma unroll
        for (int i = 0; i < NB; ++i)
            xv[i].v = *(const float4*)&sx[(b0 + i) * DX + k];
#pragma unroll
        for (int kk = 0; kk < 4; ++kk) {
            F4 wr, wz, wn;
            wr.v = __ldg(&Wih4[(k + kk) * 384 + jq]);
            wz.v = __ldg(&Wih4[(k + kk) * 384 + 128 + jq]);
            wn.v = __ldg(&Wih4[(k + kk) * 384 + 256 + jq]);
#pragma unroll
            for (int i = 0; i < NB; ++i) {
                const u64 xs2 = pack2(xv[i].f[kk]);
#pragma unroll
                for (int p = 0; p < 2; ++p) {
                    ffma2(aR[i][p],  xs2, wr.d[p]);
                    ffma2(aZ[i][p],  xs2, wz.d[p]);
                    ffma2(aIN[i][p], xs2, wn.d[p]);
                }
            }
        }
    }

    // ---- pass 2: hidden GEMM (accumulate r, z, h_n) --------------------
#pragma unroll 1
    for (int k = 0; k < Hh; k += 4) {
        F4 hv[NB];
#pragma unroll
        for (int i = 0; i < NB; ++i)
            hv[i].v = *(const float4*)&hc[(b0 + i) * Hh + k];
#pragma unroll
        for (int kk = 0; kk < 4; ++kk) {
            F4 wr, wz, wn;
            wr.v = __ldg(&Whh4[(k + kk) * 384 + jq]);
            wz.v = __ldg(&Whh4[(k + kk) * 384 + 128 + jq]);
            wn.v = __ldg(&Whh4[(k + kk) * 384 + 256 + jq]);
#pragma unroll
            for (int i = 0; i < NB; ++i) {
                const u64 hs2 = pack2(hv[i].f[kk]);
#pragma unroll
                for (int p = 0; p < 2; ++p) {
                    ffma2(aR[i][p],  hs2, wr.d[p]);
                    ffma2(aZ[i][p],  hs2, wz.d[p]);
                    ffma2(aHN[i][p], hs2, wn.d[p]);
                }
            }
        }
    }

    // ---- gate math + write h_new ----------------------------------------
    F4 bir, bhr, biz, bhz, bin, bhn;
    bir.v = __ldg((const float4*)(b_ih + j0));
    bhr.v = __ldg((const float4*)(b_hh + j0));
    biz.v = __ldg((const float4*)(b_ih + 512 + j0));
    bhz.v = __ldg((const float4*)(b_hh + 512 + j0));
    bin.v = __ldg((const float4*)(b_ih + 1024 + j0));
    bhn.v = __ldg((const float4*)(b_hh + 1024 + j0));

#pragma unroll
    for (int i = 0; i < NB; ++i) {
        F4 hold, hnew;
        hold.v = *(const float4*)&hc[(b0 + i) * Hh + j0];
#pragma unroll
        for (int p = 0; p < 2; ++p) {
            const float2 r2  = unpack2(aR[i][p]);
            const float2 z2  = unpack2(aZ[i][p]);
            const float2 in2 = unpack2(aIN[i][p]);
            const float2 hn2 = unpack2(aHN[i][p]);
            const float rv[2]  = { r2.x,  r2.y  };
            const float zv[2]  = { z2.x,  z2.y  };
            const float inv[2] = { in2.x, in2.y };
            const float hnv[2] = { hn2.x, hn2.y };
#pragma unroll
            for (int q = 0; q < 2; ++q) {
                const int l = 2 * p + q;
                const float r = sigf(rv[q] + bir.f[l] + bhr.f[l]);
                const float z = sigf(zv[q] + biz.f[l] + bhz.f[l]);
                const float nn = tanh_f(inv[q] + bin.f[l]
                                        + r * (hnv[q] + bhn.f[l]));
                hnew.f[l] = nn + z * (hold.f[l] - nn);   // (1-z)n + z h
            }
        }
        *(float4*)&hn[(b0 + i) * Hh + j0] = hnew.v;
    }
}

// ---------------------------------------------------------------------------
// Main persistent kernel: 128 blocks x 16 batch rows, loops T=96 steps.
// smem: h0 double-buffer (2x16x512) + h1 double-buffer + x (16x128) = 136KB.
// ---------------------------------------------------------------------------
__global__ void __launch_bounds__(256, 1)
gru_main(const float* __restrict__ x,
         const float* __restrict__ b_ih0, const float* __restrict__ b_hh0,
         const float* __restrict__ b_ih1, const float* __restrict__ b_hh1,
         const float* __restrict__ b_fc,  const float* __restrict__ b_pj,
         float* __restrict__ y)
{
    extern __shared__ float sm[];
    float* h0A = sm;                 // 16*512
    float* h0B = sm + 8192;
    float* h1A = sm + 16384;
    float* h1B = sm + 24576;
    float* sx  = sm + 32768;         // 16*128

    const int tid = threadIdx.x;
    const int tx = tid & 127;        // 128 float4 columns per gate
    const int ty = tid >> 7;         // 2 batch groups of 8
    const int gb0 = blockIdx.x * 16;

    // init: zero hidden states, load x[:,0,:]
    for (int i = tid; i < 8192; i += 256) { h0A[i] = 0.f; h1A[i] = 0.f; }
    for (int i = tid; i < 2048; i += 256) { sx[i] = x[gb0 * DIN + i]; }
    __syncthreads();

    float* h0c = h0A; float* h0n = h0B;
    float* h1c = h1A; float* h1n = h1B;

    for (int t = 0; t < TT; ++t) {
        // layer 0: sx (DX=128) -> h0n
        gru_layer<DIN>(sx, h0c, h0n, g_Wih0_t, g_Whh0_t, b_ih0, b_hh0, tx, ty);
        __syncthreads();

        // layer 1: h0n (DX=512) -> h1n
        gru_layer<Hh>(h0n, h1c, h1n, g_Wih1_t, g_Whh1_t, b_ih1, b_hh1, tx, ty);
        __syncthreads();

        // fc: out = h1n @ Wfc^T + b_fc  -> sx (next step input)
        {
            const int ox = tid & 31;      // 4*ox = output col base (128 cols)
            const int bz = tid >> 5;      // 2 batches per thread
            const int bb = 2 * bz;
            u64 acc[2][2];
#pragma unroll
            for (int i = 0; i < 2; ++i)
#pragma unroll
                for (int p = 0; p < 2; ++p) acc[i][p] = 0ull;

            const float4* __restrict__ W4 = (const float4*)g_Wfc_t; // [512][32]
#pragma unroll 2
            for (int k = 0; k < Hh; k += 4) {
                F4 hv0, hv1;
                hv0.v = *(const float4*)&h1n[bb * Hh + k];
                hv1.v = *(const float4*)&h1n[(bb + 1) * Hh + k];
#pragma unroll
                for (int kk = 0; kk < 4; ++kk) {
                    F4 w; w.v = __ldg(&W4[(k + kk) * 32 + ox]);
                    const u64 h0p = pack2(hv0.f[kk]);
                    const u64 h1p = pack2(hv1.f[kk]);
                    ffma2(acc[0][0], h0p, w.d[0]);
                    ffma2(acc[0][1], h0p, w.d[1]);
                    ffma2(acc[1][0], h1p, w.d[0]);
                    ffma2(acc[1][1], h1p, w.d[1]);
                }
            }
            F4 bf; bf.v = __ldg(((const float4*)b_fc) + ox);
            F4 o0, o1;
#pragma unroll
            for (int p = 0; p < 2; ++p) {
                const float2 a0 = unpack2(acc[0][p]);
                const float2 a1 = unpack2(acc[1][p]);
                o0.f[2 * p]     = a0.x + bf.f[2 * p];
                o0.f[2 * p + 1] = a0.y + bf.f[2 * p + 1];
                o1.f[2 * p]     = a1.x + bf.f[2 * p];
                o1.f[2 * p + 1] = a1.y + bf.f[2 * p + 1];
            }
            *(float4*)&sx[bb * DIN + 4 * ox]       = o0.v;
            *(float4*)&sx[(bb + 1) * DIN + 4 * ox] = o1.v;
        }
        __syncthreads();

        // projection: y[b][o][t] = sx[b] . Wpj_t[:,o] + b_pj[o]
        {
            const int bb = tid >> 4;      // 0..15
            const int ox = tid & 15;      // 4*ox = output col base (64 cols)
            F4 acc; acc.v = __ldg(((const float4*)b_pj) + ox);
            const float4* __restrict__ W4 = (const float4*)g_Wpj_t; // [128][16]
#pragma unroll 2
            for (int d = 0; d < DIN; d += 4) {
                F4 xv; xv.v = *(const float4*)&sx[bb * DIN + d];
#pragma unroll
                for (int kk = 0; kk < 4; ++kk) {
                    F4 w; w.v = __ldg(&W4[(d + kk) * 16 + ox]);
#pragma unroll
                    for (int l = 0; l < 4; ++l)
                        acc.f[l] = fmaf(xv.f[kk], w.f[l], acc.f[l]);
                }
            }
            const size_t base = ((size_t)(gb0 + bb) * DOUT + 4 * ox) * TT + t;
            y[base]          = acc.f[0];
            y[base + TT]     = acc.f[1];
            y[base + 2 * TT] = acc.f[2];
            y[base + 3 * TT] = acc.f[3];
        }

        // swap double buffers
        float* tp;
        tp = h0c; h0c = h0n; h0n = tp;
        tp = h1c; h1c = h1n; h1n = tp;
    }
}

// ---------------------------------------------------------------------------
// Entry point
// ---------------------------------------------------------------------------
extern "C" void kernel_launch(void* const* d_in, const int* in_sizes, int n_in,
                              void* d_out, int out_size)
{
    (void)in_sizes; (void)n_in; (void)out_size;

    const float* x     = (const float*)d_in[0];
    const float* Wih0  = (const float*)d_in[1];
    const float* Whh0  = (const float*)d_in[2];
    const float* bih0  = (const float*)d_in[3];
    const float* bhh0  = (const float*)d_in[4];
    const float* Wih1  = (const float*)d_in[5];
    const float* Whh1  = (const float*)d_in[6];
    const float* bih1  = (const float*)d_in[7];
    const float* bhh1  = (const float*)d_in[8];
    const float* Wfc   = (const float*)d_in[9];
    const float* bfc   = (const float*)d_in[10];
    const float* Wpj   = (const float*)d_in[11];
    const float* bpj   = (const float*)d_in[12];
    float* y = (float*)d_out;

    const int smem_bytes = (4 * 16 * Hh + 16 * DIN) * (int)sizeof(float); // 139264
    cudaFuncSetAttribute(gru_main,
                         cudaFuncAttributeMaxDynamicSharedMemorySize,
                         smem_bytes);

    reorg_kernel<<<2629632 / 256, 256>>>(Wih0, Whh0, Wih1, Whh1, Wfc, Wpj);

    gru_main<<<128, 256, smem_bytes>>>(x, bih0, bhh0, bih1, bhh1, bfc, bpj, y);
}